// round 16
// baseline (speedup 1.0000x reference)
#include <cuda_runtime.h>
#include <cuda_fp16.h>
#include <cstdint>

#define NN 65536
#define NE 1048576
#define DD 128

// ---------------- device scratch (static, allocation-free) ----------------
__device__ float g_h[NN * DD];      // residual stream
__device__ float g_xl[NN * DD];     // x @ Wl + bl
__device__ float g_xr[NN * DD];     // x @ Wr + br
__device__ int2  g_se[NE];          // CSR (by dst): packed {src, ea_bits}
__device__ int   g_cnt[NN];         // zero at load; re-zeroed by k_apply each call
__device__ int   g_off[NN + 1];
__device__ int   g_cur[NN];
__device__ int   g_bsum[256];
__device__ float g_part[1024];
__device__ float g_eamean;

__device__ __forceinline__ uint32_t pkh2(float lo, float hi) {
    __half2 h = __floats2half2_rn(lo, hi);
    return *(uint32_t*)&h;
}

__device__ __forceinline__ uint32_t smem_u32(const void* p) {
    uint32_t a;
    asm("{ .reg .u64 t; cvta.to.shared.u64 t, %1; cvt.u32.u64 %0, t; }"
        : "=r"(a) : "l"(p));
    return a;
}

// ---------------- setup 1: histogram of dst + partial sums of edge_attr ----------------
__global__ void k_prep(const int* __restrict__ dst, const float* __restrict__ ea) {
    __shared__ float sm[256];
    int base = blockIdx.x * 1024;
    float s = 0.f;
#pragma unroll
    for (int i = 0; i < 4; i++) {
        int e = base + threadIdx.x + i * 256;
        atomicAdd(&g_cnt[dst[e]], 1);
        s += ea[e];
    }
    sm[threadIdx.x] = s;
    __syncthreads();
    for (int o = 128; o > 0; o >>= 1) {
        if (threadIdx.x < o) sm[threadIdx.x] += sm[threadIdx.x + o];
        __syncthreads();
    }
    if (threadIdx.x == 0) g_part[blockIdx.x] = sm[0];
}

// ---------------- setup 2: per-256-chunk sums of g_cnt ----------------
__global__ void k_blocksum() {
    __shared__ int sm[256];
    int i = blockIdx.x * 256 + threadIdx.x;
    sm[threadIdx.x] = g_cnt[i];
    __syncthreads();
    for (int o = 128; o > 0; o >>= 1) {
        if (threadIdx.x < o) sm[threadIdx.x] += sm[threadIdx.x + o];
        __syncthreads();
    }
    if (threadIdx.x == 0) g_bsum[blockIdx.x] = sm[0];
}

// ---------------- setup 3: per-block scan + ea mean; re-zero g_cnt ----------
__global__ void k_apply() {
    __shared__ int bs[256];
    __shared__ int cs[256];
    __shared__ float fs[256];
    int tid = threadIdx.x;

    if (blockIdx.x == 0) {
        float s = g_part[tid] + g_part[tid + 256] + g_part[tid + 512] + g_part[tid + 768];
        fs[tid] = s;
    }

    int bv = g_bsum[tid];
    bs[tid] = bv;
    __syncthreads();
    for (int o = 1; o < 256; o <<= 1) {
        int t = (tid >= o) ? bs[tid - o] : 0;
        __syncthreads();
        bs[tid] += t;
        __syncthreads();
    }
    int boff = bs[blockIdx.x] - g_bsum[blockIdx.x];
    if (blockIdx.x == 255 && tid == 255) g_off[NN] = bs[255];

    int i = blockIdx.x * 256 + tid;
    int c = g_cnt[i];
    g_cnt[i] = 0;                 // ready for the next graph replay
    cs[tid] = c;
    __syncthreads();
    for (int o = 1; o < 256; o <<= 1) {
        int t = (tid >= o) ? cs[tid - o] : 0;
        __syncthreads();
        cs[tid] += t;
        __syncthreads();
    }
    int off = boff + cs[tid] - c;
    g_off[i] = off;
    g_cur[i] = off;

    if (blockIdx.x == 0) {
        for (int o = 128; o > 0; o >>= 1) {
            if (tid < o) fs[tid] += fs[tid + o];
            __syncthreads();
        }
        if (tid == 0) g_eamean = fs[0] * (1.f / (float)NE);
    }
}

// ---------------- GEMM (fp16 mma m16n8k16) + fused CSR scatter --------------
// Blocks [0,512): GEMM tiles. Blocks [512, 512+4096): scatter (layer 0 only).
#define SMPA 132
#define SMPB 136

__global__ __launch_bounds__(256, 2)
void k_gemm(const float* __restrict__ A,
            const float* __restrict__ Wl, const float* __restrict__ bl,
            const float* __restrict__ Wr, const float* __restrict__ br,
            const int* __restrict__ esrc, const int* __restrict__ edst,
            const float* __restrict__ eattr) {
    if (blockIdx.x >= 512) {  // fused scatter blocks (overlap the GEMM tail)
        int e = (blockIdx.x - 512) * 256 + threadIdx.x;
        int d = edst[e];
        int idx = atomicAdd(&g_cur[d], 1);
        g_se[idx] = make_int2(esrc[e], __float_as_int(eattr[e]));
        return;
    }

    extern __shared__ uint32_t smw[];
    uint32_t* As = smw;              // 64 frag-rows (Rg*8+kb) x SMPA words
    uint32_t* Bs = smw + 64 * SMPA;  // 32 half2-k-rows x SMPB (one K-half)

    int tid = threadIdx.x;
    int rowBase = blockIdx.x * 128;
    int lane = tid & 31, warp = tid >> 5;
    int wr = warp & 1, wc = warp >> 1;       // 2 row-groups x 4 col-groups
    int r0 = wr * 64, c0 = wc * 32;
    int g = lane >> 2, t = lane & 3;

    // load A tile once, fragment-packed fp16
#pragma unroll
    for (int i = 0; i < 16; i++) {
        int lin = tid + 256 * i;
        int r = lin >> 5;                    // 0..127
        int c4 = (lin & 31) << 2;            // 0,4,..,124
        float4 hv = *(const float4*)(A + (size_t)(rowBase + r) * DD + c4);
        int Rg = r >> 4, gg = r & 7, p = (r >> 3) & 1;
        int kb = c4 >> 4;
        int hk = (c4 & 15) >> 1;             // 0,2,4,6
        int t0 = hk & 3;                     // 0 or 2
        int q2 = hk >> 2;                    // 0 or 1
        uint32_t* pa = &As[(Rg * 8 + kb) * SMPA + gg * 16 + p + 2 * q2];
        pa[t0 * 4]       = pkh2(hv.x, hv.y);
        pa[(t0 + 1) * 4] = pkh2(hv.z, hv.w);
    }

    for (int side = 0; side < 2; side++) {
        const float* W    = side ? Wr : Wl;
        const float* bias = side ? br : bl;
        float* out        = side ? g_xr : g_xl;

        float acc[4][4][4];
#pragma unroll
        for (int mi = 0; mi < 4; mi++)
#pragma unroll
            for (int ni = 0; ni < 4; ni++)
#pragma unroll
                for (int q = 0; q < 4; q++) acc[mi][ni][q] = 0.f;

        for (int kh = 0; kh < 2; kh++) {
            __syncthreads();  // previous Bs fully consumed
#pragma unroll
            for (int i = 0; i < 4; i++) {
                int lin = tid + 256 * i;          // 1024 total
                int r2 = lin >> 5;                // 0..31 (k-pair)
                int c4 = (lin & 31) << 2;
                const float* w0 = W + (size_t)(kh * 64 + 2 * r2) * DD + c4;
                float4 wa = *(const float4*)w0;
                float4 wb = *(const float4*)(w0 + DD);
                uint32_t* pb = &Bs[r2 * SMPB + c4];
                pb[0] = pkh2(wa.x, wb.x);
                pb[1] = pkh2(wa.y, wb.y);
                pb[2] = pkh2(wa.z, wb.z);
                pb[3] = pkh2(wa.w, wb.w);
            }
            __syncthreads();

#pragma unroll
            for (int ks = 0; ks < 4; ks++) {      // 4 k16-steps per half
                int kb = kh * 4 + ks;
                uint4 a[4];
#pragma unroll
                for (int mi = 0; mi < 4; mi++) {
                    int Rg = wr * 4 + mi;
                    a[mi] = *(const uint4*)&As[(Rg * 8 + kb) * SMPA + lane * 4];
                }
#pragma unroll
                for (int ni = 0; ni < 4; ni++) {
                    int nb = c0 + ni * 8 + g;
                    uint32_t b0 = Bs[(ks * 8 + t) * SMPB + nb];
                    uint32_t b1 = Bs[(ks * 8 + t + 4) * SMPB + nb];
#pragma unroll
                    for (int mi = 0; mi < 4; mi++) {
                        asm volatile(
                            "mma.sync.aligned.m16n8k16.row.col.f32.f16.f16.f32 "
                            "{%0,%1,%2,%3},{%4,%5,%6,%7},{%8,%9},{%0,%1,%2,%3};"
                            : "+f"(acc[mi][ni][0]), "+f"(acc[mi][ni][1]),
                              "+f"(acc[mi][ni][2]), "+f"(acc[mi][ni][3])
                            : "r"(a[mi].x), "r"(a[mi].y), "r"(a[mi].z), "r"(a[mi].w),
                              "r"(b0), "r"(b1));
                    }
                }
            }
        }

#pragma unroll
        for (int mi = 0; mi < 4; mi++) {
#pragma unroll
            for (int ni = 0; ni < 4; ni++) {
                int cc = c0 + ni * 8 + 2 * t;
                float b0v = bias[cc], b1v = bias[cc + 1];
                int rr = rowBase + r0 + mi * 16 + g;
                *(float2*)(out + (size_t)rr * DD + cc) =
                    make_float2(acc[mi][ni][0] + b0v, acc[mi][ni][1] + b1v);
                *(float2*)(out + (size_t)(rr + 8) * DD + cc) =
                    make_float2(acc[mi][ni][2] + b0v, acc[mi][ni][3] + b1v);
            }
        }
    }
}

// ---------------- fused edge kernel: cp.async ring gather -------------------
// Per warp: 8-slot x 512B smem ring; edges prefetched 6 ahead (one commit
// group per edge, empty commits pad the tail so wait_group is constant).
// alpha = e^a / sum e^a (no max-shift: logits O(1), overflow-impossible).
template <int H>
__device__ __forceinline__ float edge_w(float4 x4, float4 xr4, float4 at4,
                                        float4 we4, float eav) {
    float m0 = x4.x + xr4.x + eav * we4.x;
    float m1 = x4.y + xr4.y + eav * we4.y;
    float m2 = x4.z + xr4.z + eav * we4.z;
    float m3 = x4.w + xr4.w + eav * we4.w;
    m0 = (m0 >= 0.f) ? m0 : 0.2f * m0;
    m1 = (m1 >= 0.f) ? m1 : 0.2f * m1;
    m2 = (m2 >= 0.f) ? m2 : 0.2f * m2;
    m3 = (m3 >= 0.f) ? m3 : 0.2f * m3;
    float p = m0 * at4.x + m1 * at4.y + m2 * at4.z + m3 * at4.w;
    p += __shfl_xor_sync(0xffffffffu, p, 1);
    p += __shfl_xor_sync(0xffffffffu, p, 2);
    p += __shfl_xor_sync(0xffffffffu, p, 4);
    if (H == 1) {
        p += __shfl_xor_sync(0xffffffffu, p, 8);
        p += __shfl_xor_sync(0xffffffffu, p, 16);
    }
    return __expf(p);
}

__device__ __forceinline__ void cp16(uint32_t dst, const float* src) {
    asm volatile("cp.async.ca.shared.global [%0], [%1], 16;"
                 :: "r"(dst), "l"(src));
}
__device__ __forceinline__ void cpcommit() {
    asm volatile("cp.async.commit_group;");
}

template <int H, bool LAST>
__global__ void k_edge(const float* __restrict__ hin,
                       const float* __restrict__ att, const float* __restrict__ Wev,
                       const float* __restrict__ bp, const float* __restrict__ lng,
                       const float* __restrict__ lnb, float* __restrict__ dout) {
    __shared__ float ring[8][8][128];   // [warp][slot][chan] = 32KB
    int wid = threadIdx.x >> 5;
    int n = blockIdx.x * 8 + wid;
    int l = threadIdx.x & 31;
    int col = l * 4;

    const float* myring = &ring[wid][0][0];
    uint32_t rb = smem_u32(myring) + l * 16;   // this lane's 16B slot base

    float4 xr4 = *(const float4*)(g_xr + (size_t)n * DD + col);
    float4 at4 = *(const float4*)(att + col);
    float4 we4 = *(const float4*)(Wev + col);
    int e0 = g_off[n], e1 = g_off[n + 1];
    int deg = e1 - e0;

    // prologue: prefetch 6 edges (empty commits if fewer)
#pragma unroll
    for (int i = 0; i < 6; i++) {
        if (i < deg) {
            int src = g_se[e0 + i].x;
            cp16(rb + i * 512, g_xl + (size_t)src * DD + l * 4);
        }
        cpcommit();
    }

    // self-loop in registers while transfers fly (src=n, ea=mean)
    float4 xs = *(const float4*)(g_xl + (size_t)n * DD + col);
    float ws = edge_w<H>(xs, xr4, at4, we4, g_eamean);
    float ss = ws;
    float a0 = ws * xs.x, a1 = ws * xs.y, a2 = ws * xs.z, a3 = ws * xs.w;
    float ss2 = 0.f, b0 = 0.f, b1 = 0.f, b2 = 0.f, b3 = 0.f;

    int c = 0;
    for (; c + 2 <= deg; c += 2) {
        asm volatile("cp.async.wait_group 4;");   // edges c, c+1 arrived
        int2 q0 = g_se[e0 + c];
        int2 q1 = g_se[e0 + c + 1];
        float4 xa = *(const float4*)(myring + (c & 7) * 128 + col);
        float4 xb = *(const float4*)(myring + ((c + 1) & 7) * 128 + col);
        // prefetch edges c+6, c+7 (slots differ from those just read)
#pragma unroll
        for (int j = 0; j < 2; j++) {
            int i = c + 6 + j;
            if (i < deg) {
                int src = g_se[e0 + i].x;
                cp16(rb + (i & 7) * 512, g_xl + (size_t)src * DD + l * 4);
            }
            cpcommit();
        }
        float wa = edge_w<H>(xa, xr4, at4, we4, __int_as_float(q0.y));
        float wb = edge_w<H>(xb, xr4, at4, we4, __int_as_float(q1.y));
        ss += wa;  a0 += wa * xa.x; a1 += wa * xa.y; a2 += wa * xa.z; a3 += wa * xa.w;
        ss2 += wb; b0 += wb * xb.x; b1 += wb * xb.y; b2 += wb * xb.z; b3 += wb * xb.w;
    }
    if (c < deg) {
        asm volatile("cp.async.wait_group 0;");
        int2 q0 = g_se[e0 + c];
        float4 xa = *(const float4*)(myring + (c & 7) * 128 + col);
        float wa = edge_w<H>(xa, xr4, at4, we4, __int_as_float(q0.y));
        ss += wa; a0 += wa * xa.x; a1 += wa * xa.y; a2 += wa * xa.z; a3 += wa * xa.w;
    }
    ss += ss2; a0 += b0; a1 += b1; a2 += b2; a3 += b3;

    float4 bp4 = *(const float4*)(bp + col);
    float inv = 1.f / (ss + 1e-16f);
    float o0 = a0 * inv + bp4.x;
    float o1 = a1 * inv + bp4.y;
    float o2 = a2 * inv + bp4.z;
    float o3 = a3 * inv + bp4.w;

    // LayerNorm over 128 (warp-wide reduce)
    float s1 = o0 + o1 + o2 + o3;
    s1 += __shfl_xor_sync(0xffffffffu, s1, 1);
    s1 += __shfl_xor_sync(0xffffffffu, s1, 2);
    s1 += __shfl_xor_sync(0xffffffffu, s1, 4);
    s1 += __shfl_xor_sync(0xffffffffu, s1, 8);
    s1 += __shfl_xor_sync(0xffffffffu, s1, 16);
    float mu = s1 * (1.f / 128.f);
    float d0 = o0 - mu, d1 = o1 - mu, d2 = o2 - mu, d3 = o3 - mu;
    float q = d0 * d0 + d1 * d1 + d2 * d2 + d3 * d3;
    q += __shfl_xor_sync(0xffffffffu, q, 1);
    q += __shfl_xor_sync(0xffffffffu, q, 2);
    q += __shfl_xor_sync(0xffffffffu, q, 4);
    q += __shfl_xor_sync(0xffffffffu, q, 8);
    q += __shfl_xor_sync(0xffffffffu, q, 16);
    float rs = rsqrtf(q * (1.f / 128.f) + 1e-5f);
    float4 g4 = *(const float4*)(lng + col);
    float4 b4 = *(const float4*)(lnb + col);
    float y0 = d0 * rs * g4.x + b4.x;
    float y1 = d1 * rs * g4.y + b4.y;
    float y2 = d2 * rs * g4.z + b4.z;
    float y3 = d3 * rs * g4.w + b4.w;

    if (!LAST) {  // exact GELU
        const float k = 0.70710678118654752f;
        y0 = 0.5f * y0 * (1.f + erff(y0 * k));
        y1 = 0.5f * y1 * (1.f + erff(y1 * k));
        y2 = 0.5f * y2 * (1.f + erff(y2 * k));
        y3 = 0.5f * y3 * (1.f + erff(y3 * k));
    }

    float4 h4 = *(const float4*)(hin + (size_t)n * DD + col);
    h4.x += y0; h4.y += y1; h4.z += y2; h4.w += y3;

    if (!LAST) {
        *(float4*)(g_h + (size_t)n * DD + col) = h4;
    } else {  // to_dense_batch(128, 512, 128)[:, :-1, :]
        int gi = n >> 9, ii = n & 511;
        if (ii != 511)
            *(float4*)(dout + ((size_t)(gi * 511 + ii)) * DD + col) = h4;
    }
}

// ---------------- launch ----------------
extern "C" void kernel_launch(void* const* d_in, const int* in_sizes, int n_in,
                              void* d_out, int out_size) {
    const float* x     = (const float*)d_in[0];
    const int*   esrc  = (const int*)d_in[1];
    const int*   edst  = (const int*)d_in[2];
    const float* eattr = (const float*)d_in[3];
    const float* Wl    = (const float*)d_in[4];
    const float* bl    = (const float*)d_in[5];
    const float* Wr    = (const float*)d_in[6];
    const float* br    = (const float*)d_in[7];
    const float* We    = (const float*)d_in[8];
    const float* att   = (const float*)d_in[9];
    const float* bp    = (const float*)d_in[10];
    const float* lng   = (const float*)d_in[11];
    const float* lnb   = (const float*)d_in[12];
    float* out = (float*)d_out;

    void* p_h = 0; cudaGetSymbolAddress(&p_h, g_h);

    const int GSM = 64 * SMPA * 4 + 32 * SMPB * 4;  // 51200 B -> 2 CTAs/SM
    cudaFuncSetAttribute(k_gemm, cudaFuncAttributeMaxDynamicSharedMemorySize, GSM);

    k_prep<<<1024, 256>>>(edst, eattr);
    k_blocksum<<<256, 256>>>();
    k_apply<<<256, 256>>>();
    // layer-0 GEMM + fused scatter (scatter blocks fill the GEMM tail)
    k_gemm<<<512 + NE / 256, 256, GSM>>>(x, Wl, bl, Wr, br, esrc, edst, eattr);

    const float* hsrc = (const float*)p_h;
    // 5th launch: layer-0 edge (profiler capture slot)
    k_edge<4, false><<<NN / 8, 256>>>(x, att, We, bp, lng, lnb, out);
    for (int i = 1; i < 3; i++) {
        k_gemm<<<512, 256, GSM>>>(
            hsrc, Wl + i * 16384, bl + i * 128, Wr + i * 16384, br + i * 128,
            esrc, edst, eattr);
        if (i < 2)
            k_edge<4, false><<<NN / 8, 256>>>(hsrc, att + i * 128, We + i * 128, bp + i * 128,
                                              lng + i * 128, lnb + i * 128, out);
        else
            k_edge<1, true><<<NN / 8, 256>>>(hsrc, att + i * 128, We + i * 128, bp + i * 128,
                                             lng + i * 128, lnb + i * 128, out);
    }
}

// round 17
// speedup vs baseline: 1.1078x; 1.1078x over previous
#include <cuda_runtime.h>
#include <cuda_fp16.h>
#include <cstdint>

#define NN 65536
#define NE 1048576
#define DD 128

// ---------------- device scratch (static, allocation-free) ----------------
__device__ float g_h[NN * DD];      // residual stream
__device__ float g_xl[NN * DD];     // x @ Wl + bl
__device__ float g_xr[NN * DD];     // x @ Wr + br
__device__ int2  g_se[NE];          // CSR (by dst): packed {src, ea_bits}
__device__ int   g_cnt[NN];         // zero at load; re-zeroed by k_apply each call
__device__ int   g_off[NN + 1];
__device__ int   g_cur[NN];
__device__ int   g_bsum[256];
__device__ float g_part[1024];
__device__ float g_eamean;
__device__ uint32_t g_pW[3 * 2 * 64 * 128];  // prepacked fp16 (k,k+1)-pair weights

__device__ __forceinline__ uint32_t pkh2(float lo, float hi) {
    __half2 h = __floats2half2_rn(lo, hi);
    return *(uint32_t*)&h;
}

__device__ __forceinline__ uint32_t smem_u32(const void* p) {
    uint32_t a;
    asm("{ .reg .u64 t; cvta.to.shared.u64 t, %1; cvt.u32.u64 %0, t; }"
        : "=r"(a) : "l"(p));
    return a;
}
__device__ __forceinline__ void cpg16(uint32_t dst, const uint32_t* src) {
    asm volatile("cp.async.ca.shared.global [%0], [%1], 16;" :: "r"(dst), "l"(src));
}

// ---- packed f32x2 helpers (FFMA2 path) ----
__device__ __forceinline__ uint64_t f2pack(float lo, float hi) {
    uint64_t r; asm("mov.b64 %0, {%1,%2};" : "=l"(r) : "f"(lo), "f"(hi)); return r;
}
__device__ __forceinline__ float2 f2unpack(uint64_t a) {
    uint32_t lo, hi; asm("mov.b64 {%0,%1}, %2;" : "=r"(lo), "=r"(hi) : "l"(a));
    return make_float2(__uint_as_float(lo), __uint_as_float(hi));
}
__device__ __forceinline__ uint64_t f2add(uint64_t a, uint64_t b) {
    uint64_t r; asm("add.rn.f32x2 %0,%1,%2;" : "=l"(r) : "l"(a), "l"(b)); return r;
}
__device__ __forceinline__ uint64_t f2mul(uint64_t a, uint64_t b) {
    uint64_t r; asm("mul.rn.f32x2 %0,%1,%2;" : "=l"(r) : "l"(a), "l"(b)); return r;
}
__device__ __forceinline__ uint64_t f2fma(uint64_t a, uint64_t b, uint64_t c) {
    uint64_t r; asm("fma.rn.f32x2 %0,%1,%2,%3;" : "=l"(r) : "l"(a), "l"(b), "l"(c)); return r;
}

// ---------------- setup 1: histogram of dst + partial sums of edge_attr ----------------
__global__ void k_prep(const int* __restrict__ dst, const float* __restrict__ ea) {
    __shared__ float sm[256];
    int base = blockIdx.x * 1024;
    float s = 0.f;
#pragma unroll
    for (int i = 0; i < 4; i++) {
        int e = base + threadIdx.x + i * 256;
        atomicAdd(&g_cnt[dst[e]], 1);
        s += ea[e];
    }
    sm[threadIdx.x] = s;
    __syncthreads();
    for (int o = 128; o > 0; o >>= 1) {
        if (threadIdx.x < o) sm[threadIdx.x] += sm[threadIdx.x + o];
        __syncthreads();
    }
    if (threadIdx.x == 0) g_part[blockIdx.x] = sm[0];
}

// ---------------- setup 1b: prepack all 6 weight matrices to fp16 pairs -----
__global__ void k_packW(const float* __restrict__ Wl, const float* __restrict__ Wr) {
    int idx = blockIdx.x * 1024 + threadIdx.x;   // 0..49151
    int layer = idx >> 14;
    int rem = idx & 16383;
    int side = rem >> 13;
    int r2 = (rem >> 7) & 63;
    int c = rem & 127;
    const float* W = (side ? Wr : Wl) + layer * 16384;
    g_pW[idx] = pkh2(W[(2 * r2) * 128 + c], W[(2 * r2 + 1) * 128 + c]);
}

// ---------------- setup 2: per-256-chunk sums of g_cnt ----------------
__global__ void k_blocksum() {
    __shared__ int sm[256];
    int i = blockIdx.x * 256 + threadIdx.x;
    sm[threadIdx.x] = g_cnt[i];
    __syncthreads();
    for (int o = 128; o > 0; o >>= 1) {
        if (threadIdx.x < o) sm[threadIdx.x] += sm[threadIdx.x + o];
        __syncthreads();
    }
    if (threadIdx.x == 0) g_bsum[blockIdx.x] = sm[0];
}

// ---------------- setup 3: per-block scan + ea mean; re-zero g_cnt ----------
__global__ void k_apply() {
    __shared__ int bs[256];
    __shared__ int cs[256];
    __shared__ float fs[256];
    int tid = threadIdx.x;

    if (blockIdx.x == 0) {
        float s = g_part[tid] + g_part[tid + 256] + g_part[tid + 512] + g_part[tid + 768];
        fs[tid] = s;
    }

    int bv = g_bsum[tid];
    bs[tid] = bv;
    __syncthreads();
    for (int o = 1; o < 256; o <<= 1) {
        int t = (tid >= o) ? bs[tid - o] : 0;
        __syncthreads();
        bs[tid] += t;
        __syncthreads();
    }
    int boff = bs[blockIdx.x] - g_bsum[blockIdx.x];
    if (blockIdx.x == 255 && tid == 255) g_off[NN] = bs[255];

    int i = blockIdx.x * 256 + tid;
    int c = g_cnt[i];
    g_cnt[i] = 0;                 // ready for the next graph replay
    cs[tid] = c;
    __syncthreads();
    for (int o = 1; o < 256; o <<= 1) {
        int t = (tid >= o) ? cs[tid - o] : 0;
        __syncthreads();
        cs[tid] += t;
        __syncthreads();
    }
    int off = boff + cs[tid] - c;
    g_off[i] = off;
    g_cur[i] = off;

    if (blockIdx.x == 0) {
        for (int o = 128; o > 0; o >>= 1) {
            if (tid < o) fs[tid] += fs[tid + o];
            __syncthreads();
        }
        if (tid == 0) g_eamean = fs[0] * (1.f / (float)NE);
    }
}

// ---------------- GEMM (fp16 mma, cp.async double-buffered B) + scatter -----
// Blocks [0,512): GEMM tiles. Blocks [512, 512+4096): scatter (layer 0 only).
#define SMPA 132
#define SMPB 136

__global__ __launch_bounds__(256, 2)
void k_gemm(const float* __restrict__ A,
            const float* __restrict__ bl, const float* __restrict__ br,
            const uint32_t* __restrict__ pL,   // prepacked W for this layer
            const int* __restrict__ esrc, const int* __restrict__ edst,
            const float* __restrict__ eattr) {
    if (blockIdx.x >= 512) {  // fused scatter blocks (overlap the GEMM tail)
        int e = (blockIdx.x - 512) * 256 + threadIdx.x;
        int d = edst[e];
        int idx = atomicAdd(&g_cur[d], 1);
        g_se[idx] = make_int2(esrc[e], __float_as_int(eattr[e]));
        return;
    }

    extern __shared__ uint32_t smw[];
    uint32_t* As = smw;                         // 64 frag-rows x SMPA words
    uint32_t* Bsb[2] = { smw + 64 * SMPA, smw + 64 * SMPA + 32 * SMPB };
    uint32_t sb0 = smem_u32(smw + 64 * SMPA);
    uint32_t sb1 = sb0 + 32 * SMPB * 4;

    int tid = threadIdx.x;
    int rowBase = blockIdx.x * 128;
    int lane = tid & 31, warp = tid >> 5;
    int wr = warp & 1, wc = warp >> 1;       // 2 row-groups x 4 col-groups
    int r0 = wr * 64, c0 = wc * 32;
    int g = lane >> 2, t = lane & 3;

    // cp.async chunk assignment for B: 4 chunks/thread
    int br2[4], bc4[4];
#pragma unroll
    for (int i = 0; i < 4; i++) {
        int lin = tid + 256 * i;
        br2[i] = lin >> 5;
        bc4[i] = (lin & 31) << 2;
    }

    // prologue: phase 0 (side 0, kh 0) B copy in flight during A-tile load
#pragma unroll
    for (int i = 0; i < 4; i++)
        cpg16(sb0 + (br2[i] * SMPB + bc4[i]) * 4, pL + br2[i] * 128 + bc4[i]);
    asm volatile("cp.async.commit_group;");

    // load A tile once, fragment-packed fp16
#pragma unroll
    for (int i = 0; i < 16; i++) {
        int lin = tid + 256 * i;
        int r = lin >> 5;                    // 0..127
        int c4 = (lin & 31) << 2;            // 0,4,..,124
        float4 hv = *(const float4*)(A + (size_t)(rowBase + r) * DD + c4);
        int Rg = r >> 4, gg = r & 7, p = (r >> 3) & 1;
        int kb = c4 >> 4;
        int hk = (c4 & 15) >> 1;
        int t0 = hk & 3;
        int q2 = hk >> 2;
        uint32_t* pa = &As[(Rg * 8 + kb) * SMPA + gg * 16 + p + 2 * q2];
        pa[t0 * 4]       = pkh2(hv.x, hv.y);
        pa[(t0 + 1) * 4] = pkh2(hv.z, hv.w);
    }

    for (int side = 0; side < 2; side++) {
        const float* bias = side ? br : bl;
        float* out        = side ? g_xr : g_xl;

        float acc[4][4][4];
#pragma unroll
        for (int mi = 0; mi < 4; mi++)
#pragma unroll
            for (int ni = 0; ni < 4; ni++)
#pragma unroll
                for (int q = 0; q < 4; q++) acc[mi][ni][q] = 0.f;

        for (int kh = 0; kh < 2; kh++) {
            int ph = side * 2 + kh;
            if (ph < 3) {  // issue next phase's B copy into the other buffer
                int s2 = (ph + 1) >> 1, k2 = (ph + 1) & 1;
                uint32_t db = ((ph + 1) & 1) ? sb1 : sb0;
                const uint32_t* sp = pL + s2 * 8192 + k2 * 4096;
#pragma unroll
                for (int i = 0; i < 4; i++)
                    cpg16(db + (br2[i] * SMPB + bc4[i]) * 4, sp + br2[i] * 128 + bc4[i]);
                asm volatile("cp.async.commit_group;");
                asm volatile("cp.async.wait_group 1;");
            } else {
                asm volatile("cp.async.wait_group 0;");
            }
            __syncthreads();   // phase ph's B (and A on ph=0) visible block-wide

            const uint32_t* Bs = Bsb[ph & 1];
#pragma unroll
            for (int ks = 0; ks < 4; ks++) {      // 4 k16-steps per half
                int kb = kh * 4 + ks;
                uint4 a[4];
#pragma unroll
                for (int mi = 0; mi < 4; mi++) {
                    int Rg = wr * 4 + mi;
                    a[mi] = *(const uint4*)&As[(Rg * 8 + kb) * SMPA + lane * 4];
                }
#pragma unroll
                for (int ni = 0; ni < 4; ni++) {
                    int nb = c0 + ni * 8 + g;
                    uint32_t b0 = Bs[(ks * 8 + t) * SMPB + nb];
                    uint32_t b1 = Bs[(ks * 8 + t + 4) * SMPB + nb];
#pragma unroll
                    for (int mi = 0; mi < 4; mi++) {
                        asm volatile(
                            "mma.sync.aligned.m16n8k16.row.col.f32.f16.f16.f32 "
                            "{%0,%1,%2,%3},{%4,%5,%6,%7},{%8,%9},{%0,%1,%2,%3};"
                            : "+f"(acc[mi][ni][0]), "+f"(acc[mi][ni][1]),
                              "+f"(acc[mi][ni][2]), "+f"(acc[mi][ni][3])
                            : "r"(a[mi].x), "r"(a[mi].y), "r"(a[mi].z), "r"(a[mi].w),
                              "r"(b0), "r"(b1));
                    }
                }
            }
            __syncthreads();   // all reads of this buffer done before its reuse
        }

#pragma unroll
        for (int mi = 0; mi < 4; mi++) {
#pragma unroll
            for (int ni = 0; ni < 4; ni++) {
                int cc = c0 + ni * 8 + 2 * t;
                float b0v = bias[cc], b1v = bias[cc + 1];
                int rr = rowBase + r0 + mi * 16 + g;
                *(float2*)(out + (size_t)rr * DD + cc) =
                    make_float2(acc[mi][ni][0] + b0v, acc[mi][ni][1] + b1v);
                *(float2*)(out + (size_t)(rr + 8) * DD + cc) =
                    make_float2(acc[mi][ni][2] + b0v, acc[mi][ni][3] + b1v);
            }
        }
    }
}

// ---------------- fused edge kernel: f32x2 math, 2-way chains (R12 body) ----
// alpha = e^a / sum e^a (no max-shift: logits O(1), overflow-impossible).
// leaky(m) = 0.6m + 0.4|m|.
template <int H>
__device__ __forceinline__ float edge_w2(uint64_t x0, uint64_t x1,
                                         uint64_t xr0, uint64_t xr1,
                                         uint64_t at0, uint64_t at1,
                                         uint64_t we0, uint64_t we1,
                                         uint64_t ea2, uint64_t C06, uint64_t C04) {
    uint64_t m0 = f2fma(we0, ea2, f2add(x0, xr0));
    uint64_t m1 = f2fma(we1, ea2, f2add(x1, xr1));
    uint64_t b0 = m0 & 0x7FFFFFFF7FFFFFFFull;
    uint64_t b1 = m1 & 0x7FFFFFFF7FFFFFFFull;
    uint64_t l0 = f2fma(m0, C06, f2mul(b0, C04));
    uint64_t l1 = f2fma(m1, C06, f2mul(b1, C04));
    uint64_t p2 = f2fma(l1, at1, f2mul(l0, at0));
    float2 pf = f2unpack(p2);
    float p = pf.x + pf.y;
    p += __shfl_xor_sync(0xffffffffu, p, 1);
    p += __shfl_xor_sync(0xffffffffu, p, 2);
    p += __shfl_xor_sync(0xffffffffu, p, 4);
    if (H == 1) {
        p += __shfl_xor_sync(0xffffffffu, p, 8);
        p += __shfl_xor_sync(0xffffffffu, p, 16);
    }
    return __expf(p);
}

template <int H, bool LAST>
__global__ void k_edge(const float* __restrict__ hin,
                       const float* __restrict__ att, const float* __restrict__ Wev,
                       const float* __restrict__ bp, const float* __restrict__ lng,
                       const float* __restrict__ lnb, float* __restrict__ dout) {
    int n = blockIdx.x * 8 + (threadIdx.x >> 5);
    int l = threadIdx.x & 31;
    int col = l * 4;

    ulonglong2 xr2 = *(const ulonglong2*)(g_xr + (size_t)n * DD + col);
    ulonglong2 at2 = *(const ulonglong2*)(att + col);
    ulonglong2 we2 = *(const ulonglong2*)(Wev + col);
    const uint64_t C06 = f2pack(0.6f, 0.6f), C04 = f2pack(0.4f, 0.4f);
    int e0 = g_off[n], e1 = g_off[n + 1];

    // self-loop first (src=n, ea=mean)
    ulonglong2 xs = *(const ulonglong2*)(g_xl + (size_t)n * DD + col);
    float eam = g_eamean;
    float ws = edge_w2<H>(xs.x, xs.y, xr2.x, xr2.y, at2.x, at2.y,
                          we2.x, we2.y, f2pack(eam, eam), C06, C04);
    uint64_t wsp = f2pack(ws, ws);
    float sA = ws, sB = 0.f;
    uint64_t A0 = f2mul(xs.x, wsp), A1 = f2mul(xs.y, wsp);
    uint64_t B0 = 0, B1 = 0;

    int e = e0;
    for (; e + 2 <= e1; e += 2) {  // two independent chains
        int2 q0 = g_se[e];
        int2 q1 = g_se[e + 1];
        ulonglong2 xa = *(const ulonglong2*)(g_xl + (size_t)q0.x * DD + col);
        ulonglong2 xb = *(const ulonglong2*)(g_xl + (size_t)q1.x * DD + col);
        float ea0 = __int_as_float(q0.y), ea1 = __int_as_float(q1.y);
        float wa = edge_w2<H>(xa.x, xa.y, xr2.x, xr2.y, at2.x, at2.y,
                              we2.x, we2.y, f2pack(ea0, ea0), C06, C04);
        float wb = edge_w2<H>(xb.x, xb.y, xr2.x, xr2.y, at2.x, at2.y,
                              we2.x, we2.y, f2pack(ea1, ea1), C06, C04);
        uint64_t wap = f2pack(wa, wa), wbp = f2pack(wb, wb);
        sA += wa; A0 = f2fma(xa.x, wap, A0); A1 = f2fma(xa.y, wap, A1);
        sB += wb; B0 = f2fma(xb.x, wbp, B0); B1 = f2fma(xb.y, wbp, B1);
    }
    if (e < e1) {
        int2 q0 = g_se[e];
        ulonglong2 xa = *(const ulonglong2*)(g_xl + (size_t)q0.x * DD + col);
        float ea0 = __int_as_float(q0.y);
        float wa = edge_w2<H>(xa.x, xa.y, xr2.x, xr2.y, at2.x, at2.y,
                              we2.x, we2.y, f2pack(ea0, ea0), C06, C04);
        uint64_t wap = f2pack(wa, wa);
        sA += wa; A0 = f2fma(xa.x, wap, A0); A1 = f2fma(xa.y, wap, A1);
    }
    float ss = sA + sB;
    float2 f0 = f2unpack(f2add(A0, B0));
    float2 f1 = f2unpack(f2add(A1, B1));
    float a0 = f0.x, a1 = f0.y, a2 = f1.x, a3 = f1.y;

    float4 bp4 = *(const float4*)(bp + col);
    float inv = 1.f / (ss + 1e-16f);
    float o0 = a0 * inv + bp4.x;
    float o1 = a1 * inv + bp4.y;
    float o2 = a2 * inv + bp4.z;
    float o3 = a3 * inv + bp4.w;

    // LayerNorm over 128 (warp-wide reduce)
    float s1 = o0 + o1 + o2 + o3;
    s1 += __shfl_xor_sync(0xffffffffu, s1, 1);
    s1 += __shfl_xor_sync(0xffffffffu, s1, 2);
    s1 += __shfl_xor_sync(0xffffffffu, s1, 4);
    s1 += __shfl_xor_sync(0xffffffffu, s1, 8);
    s1 += __shfl_xor_sync(0xffffffffu, s1, 16);
    float mu = s1 * (1.f / 128.f);
    float d0 = o0 - mu, d1 = o1 - mu, d2 = o2 - mu, d3 = o3 - mu;
    float q = d0 * d0 + d1 * d1 + d2 * d2 + d3 * d3;
    q += __shfl_xor_sync(0xffffffffu, q, 1);
    q += __shfl_xor_sync(0xffffffffu, q, 2);
    q += __shfl_xor_sync(0xffffffffu, q, 4);
    q += __shfl_xor_sync(0xffffffffu, q, 8);
    q += __shfl_xor_sync(0xffffffffu, q, 16);
    float rs = rsqrtf(q * (1.f / 128.f) + 1e-5f);
    float4 g4 = *(const float4*)(lng + col);
    float4 b4 = *(const float4*)(lnb + col);
    float y0 = d0 * rs * g4.x + b4.x;
    float y1 = d1 * rs * g4.y + b4.y;
    float y2 = d2 * rs * g4.z + b4.z;
    float y3 = d3 * rs * g4.w + b4.w;

    if (!LAST) {  // exact GELU
        const float k = 0.70710678118654752f;
        y0 = 0.5f * y0 * (1.f + erff(y0 * k));
        y1 = 0.5f * y1 * (1.f + erff(y1 * k));
        y2 = 0.5f * y2 * (1.f + erff(y2 * k));
        y3 = 0.5f * y3 * (1.f + erff(y3 * k));
    }

    float4 h4 = *(const float4*)(hin + (size_t)n * DD + col);
    h4.x += y0; h4.y += y1; h4.z += y2; h4.w += y3;

    if (!LAST) {
        *(float4*)(g_h + (size_t)n * DD + col) = h4;
    } else {  // to_dense_batch(128, 512, 128)[:, :-1, :]
        int gi = n >> 9, ii = n & 511;
        if (ii != 511)
            *(float4*)(dout + ((size_t)(gi * 511 + ii)) * DD + col) = h4;
    }
}

// ---------------- launch ----------------
extern "C" void kernel_launch(void* const* d_in, const int* in_sizes, int n_in,
                              void* d_out, int out_size) {
    const float* x     = (const float*)d_in[0];
    const int*   esrc  = (const int*)d_in[1];
    const int*   edst  = (const int*)d_in[2];
    const float* eattr = (const float*)d_in[3];
    const float* Wl    = (const float*)d_in[4];
    const float* bl    = (const float*)d_in[5];
    const float* Wr    = (const float*)d_in[6];
    const float* br    = (const float*)d_in[7];
    const float* We    = (const float*)d_in[8];
    const float* att   = (const float*)d_in[9];
    const float* bp    = (const float*)d_in[10];
    const float* lng   = (const float*)d_in[11];
    const float* lnb   = (const float*)d_in[12];
    float* out = (float*)d_out;

    void* p_h = 0;  cudaGetSymbolAddress(&p_h, g_h);
    void* p_pw = 0; cudaGetSymbolAddress(&p_pw, g_pW);
    const uint32_t* pW = (const uint32_t*)p_pw;

    const int GSM = 64 * SMPA * 4 + 2 * 32 * SMPB * 4;  // 68608 B -> 2 CTAs/SM
    cudaFuncSetAttribute(k_gemm, cudaFuncAttributeMaxDynamicSharedMemorySize, GSM);

    k_prep<<<1024, 256>>>(edst, eattr);
    k_packW<<<48, 1024>>>(Wl, Wr);
    k_blocksum<<<256, 256>>>();
    k_apply<<<256, 256>>>();
    // layer-0 GEMM + fused scatter (scatter blocks fill the GEMM tail)
    k_gemm<<<512 + NE / 256, 256, GSM>>>(x, bl, br, pW, esrc, edst, eattr);

    const float* hsrc = (const float*)p_h;
    k_edge<4, false><<<NN / 8, 256>>>(x, att, We, bp, lng, lnb, out);
    for (int i = 1; i < 3; i++) {
        k_gemm<<<512, 256, GSM>>>(
            hsrc, bl + i * 128, br + i * 128, pW + i * 16384, esrc, edst, eattr);
        if (i < 2)
            k_edge<4, false><<<NN / 8, 256>>>(hsrc, att + i * 128, We + i * 128, bp + i * 128,
                                              lng + i * 128, lnb + i * 128, out);
        else
            k_edge<1, true><<<NN / 8, 256>>>(hsrc, att + i * 128, We + i * 128, bp + i * 128,
                                             lng + i * 128, lnb + i * 128, out);
    }
}